// round 15
// baseline (speedup 1.0000x reference)
#include <cuda_runtime.h>
#include <stdint.h>

#define D        256
#define MITEMS   16
#define TPB      256
#define NWARP    8
#define GRID     296           // 2 blocks/SM x 148: exactly one wave
#define RPW      56            // rows per warp: 296*8*56 = 132608 >= 131072
#define TILE     64
#define CHUNK    8             // dims per pipeline chunk (32 B per row)
#define NCH      32
#define NBUF     3
#define QSTR     12            // staging row stride: 48B, LDS.128 conflict-free
#define BUFW     (TILE * QSTR) // 768 floats
#define RINGW    (NBUF * BUFW) // 2304 floats per warp
#define SM_MT    (NWARP * RINGW)          // 18432: mem_t offset
#define SMEM1_FLOATS (SM_MT + MITEMS * D) // 22528 floats = 90112 B -> 2 blocks/SM
#define SMEM1_BYTES  (SMEM1_FLOATS * 4)
#define NROWS_MAX 131072
#define NEG_BIG (-1e30f)

typedef unsigned long long u64;

// dense pre-packed weights: per row 16 u64 (each = weight duplicated in both halves)
__device__ u64 g_w[(size_t)NROWS_MAX * MITEMS];

__device__ __forceinline__ u64 pack2(float lo, float hi) {
    u64 r; asm("mov.b64 %0, {%1, %2};" : "=l"(r) : "f"(lo), "f"(hi)); return r;
}
__device__ __forceinline__ void unpack2(u64 v, float& lo, float& hi) {
    asm("mov.b64 {%0, %1}, %2;" : "=f"(lo), "=f"(hi) : "l"(v));
}
#define FMA2(d, a, b) asm("fma.rn.f32x2 %0, %1, %2, %0;" : "+l"(d) : "l"(a), "l"(b))
#define CP16(dst, src) \
    asm volatile("cp.async.cg.shared.global [%0], [%1], 16;" :: "r"(dst), "l"(src))
#define CPCOMMIT() asm volatile("cp.async.commit_group;")
#define CPWAIT(n)  asm volatile("cp.async.wait_group %0;" :: "n"(n))

// ============================ Kernel 1: dot + top-4 + softmax ============================
__global__ void __launch_bounds__(TPB, 2) epm_dot_kernel(
    const float* __restrict__ q,
    const float* __restrict__ mem,
    float* __restrict__ out_max,
    int nrows)
{
    extern __shared__ __align__(16) float sh[];
    const int tid  = threadIdx.x;
    const int wid  = tid >> 5;
    const int lane = tid & 31;

    float* ring  = sh + wid * RINGW;
    float* mem_t = sh + SM_MT;     // [dim][16 items], item pairs contiguous
    const uint32_t ring_s = (uint32_t)__cvta_generic_to_shared(ring);

    const int base = (blockIdx.x * NWARP + wid) * RPW;
    int tr = nrows - base;
    if (tr > RPW) tr = RPW;

    const int rsub = lane >> 1;    // 0..15
    const int sub  = lane & 1;     // 16B slot

    // prologue: issue chunks 0..2 before the setup barrier
    if (tr > 0) {
        #pragma unroll
        for (int c0 = 0; c0 < 3; c0++) {
            #pragma unroll
            for (int j = 0; j < 4; j++) {
                int rl = rsub + 16 * j;
                if (rl < tr) {
                    const float* src = q + (size_t)(base + rl) * D + c0 * CHUNK + sub * 4;
                    uint32_t dst = ring_s + (uint32_t)(c0 * BUFW + rl * QSTR + sub * 4) * 4u;
                    CP16(dst, src);
                }
            }
            CPCOMMIT();
        }
    }

    // cooperative setup: mem_t item-pair transpose
    #pragma unroll
    for (int i = 0; i < (MITEMS * D) / TPB; i++) {    // 16 iters
        int idx = tid + TPB * i;
        mem_t[(idx & 255) * MITEMS + (idx >> 8)] = mem[idx];
    }
    __syncthreads();    // only block barrier

    if (tr <= 0) return;

    u64 accA[8], accB[8];
    u64 ssqA2 = 0ull, ssqB2 = 0ull;
    #pragma unroll
    for (int p = 0; p < 8; p++) { accA[p] = 0ull; accB[p] = 0ull; }

    #pragma unroll 1
    for (int ct = 0; ct < NCH; ct++) {
        if (ct + 2 < NCH)      { CPWAIT(2); }
        else if (ct + 1 < NCH) { CPWAIT(1); }
        else                   { CPWAIT(0); }
        __syncwarp();

        const float* qb = ring + (ct % NBUF) * BUFW;
        #pragma unroll
        for (int h = 0; h < 2; h++) {
            ulonglong2 qA = *(const ulonglong2*)(qb + lane * QSTR + 4 * h);
            ulonglong2 qB = *(const ulonglong2*)(qb + (lane + 32) * QSTR + 4 * h);
            FMA2(ssqA2, qA.x, qA.x); FMA2(ssqA2, qA.y, qA.y);
            FMA2(ssqB2, qB.x, qB.x); FMA2(ssqB2, qB.y, qB.y);
            float a0, a1, a2, a3, b0, b1, b2, b3;
            unpack2(qA.x, a0, a1); unpack2(qA.y, a2, a3);
            unpack2(qB.x, b0, b1); unpack2(qB.y, b2, b3);
            u64 qqA[4] = {pack2(a0,a0), pack2(a1,a1), pack2(a2,a2), pack2(a3,a3)};
            u64 qqB[4] = {pack2(b0,b0), pack2(b1,b1), pack2(b2,b2), pack2(b3,b3)};
            #pragma unroll
            for (int d = 0; d < 4; d++) {
                const ulonglong2* mt =
                    (const ulonglong2*)(mem_t + (ct * CHUNK + 4 * h + d) * MITEMS);
                ulonglong2 v0 = mt[0], v1 = mt[1], v2 = mt[2], v3 = mt[3];
                FMA2(accA[0], v0.x, qqA[d]); FMA2(accA[1], v0.y, qqA[d]);
                FMA2(accA[2], v1.x, qqA[d]); FMA2(accA[3], v1.y, qqA[d]);
                FMA2(accA[4], v2.x, qqA[d]); FMA2(accA[5], v2.y, qqA[d]);
                FMA2(accA[6], v3.x, qqA[d]); FMA2(accA[7], v3.y, qqA[d]);
                FMA2(accB[0], v0.x, qqB[d]); FMA2(accB[1], v0.y, qqB[d]);
                FMA2(accB[2], v1.x, qqB[d]); FMA2(accB[3], v1.y, qqB[d]);
                FMA2(accB[4], v2.x, qqB[d]); FMA2(accB[5], v2.y, qqB[d]);
                FMA2(accB[6], v3.x, qqB[d]); FMA2(accB[7], v3.y, qqB[d]);
            }
        }
        __syncwarp();
        if (ct + 3 < NCH) {
            #pragma unroll
            for (int j = 0; j < 4; j++) {
                int rl = rsub + 16 * j;
                if (rl < tr) {
                    const float* src = q + (size_t)(base + rl) * D + (ct + 3) * CHUNK + sub * 4;
                    uint32_t dst = ring_s +
                        (uint32_t)(((ct + 3) % NBUF) * BUFW + rl * QSTR + sub * 4) * 4u;
                    CP16(dst, src);
                }
            }
            CPCOMMIT();
        }
    }

    // epilogue: 2 rows per lane -> out_max + pre-packed dense weights in g_w
    #pragma unroll
    for (int r = 0; r < 2; r++) {
        int rl = lane + 32 * r;
        float s[MITEMS];
        #pragma unroll
        for (int p = 0; p < 8; p++)
            unpack2(r == 0 ? accA[p] : accB[p], s[2 * p], s[2 * p + 1]);
        float sl, shi; unpack2(r == 0 ? ssqA2 : ssqB2, sl, shi);
        float inv = rsqrtf(fmaxf(sl + shi, 1e-24f)) * 10.0f;  // (1/|q|)/tau; mem unit-norm
        #pragma unroll
        for (int m = 0; m < MITEMS; m++) s[m] *= inv;

        float bw[4]; int bi[4];
        #pragma unroll
        for (int k = 0; k < 4; k++) {
            float best = NEG_BIG; int b = 0;
            #pragma unroll
            for (int m = 0; m < MITEMS; m++)
                if (s[m] > best) { best = s[m]; b = m; }      // first-index ties
            bw[k] = best; bi[k] = b;
            #pragma unroll
            for (int m = 0; m < MITEMS; m++)
                s[m] = (m == b) ? NEG_BIG : s[m];
        }
        float e1 = __expf(bw[1] - bw[0]);
        float e2 = __expf(bw[2] - bw[0]);
        float e3 = __expf(bw[3] - bw[0]);
        float rden = 1.0f / (1.0f + e1 + e2 + e3);

        if (rl < tr) {
            size_t row = (size_t)(base + rl);
            u64* Wd = g_w + row * MITEMS;
            ulonglong2 z; z.x = 0ull; z.y = 0ull;
            #pragma unroll
            for (int t = 0; t < 8; t++) ((ulonglong2*)Wd)[t] = z;
            // same-thread same-address ordering: scatters land after zeros
            Wd[bi[0]] = pack2(rden,        rden);
            Wd[bi[1]] = pack2(e1 * rden,   e1 * rden);
            Wd[bi[2]] = pack2(e2 * rden,   e2 * rden);
            Wd[bi[3]] = pack2(e3 * rden,   e3 * rden);
            out_max[row] = bw[0];
        }
    }
}

// ============================ Kernel 2: dense blend (write stream) ============================
__global__ void __launch_bounds__(TPB, 2) epm_blend_kernel(
    const float* __restrict__ mem,
    float* __restrict__ out_ret,
    int nrows)
{
    const int tid  = threadIdx.x;
    const int wid  = tid >> 5;
    const int lane = tid & 31;

    const int base = (blockIdx.x * NWARP + wid) * RPW;
    int tr = nrows - base;
    if (tr > RPW) tr = RPW;
    if (tr <= 0) return;

    const ulonglong2* mg = (const ulonglong2*)mem;   // [item][64 x 16B]

    #pragma unroll 1
    for (int p = 0; p < 2; p++) {                    // two half-passes cap reg pressure
        ulonglong2 V[MITEMS];                        // static indexing only
        #pragma unroll
        for (int m = 0; m < MITEMS; m++)
            V[m] = mg[m * (D / 4) + p * 32 + lane];  // L1/L2-hot after first warp

        #pragma unroll 2
        for (int j = 0; j < RPW; j++) {
            if (j >= tr) break;
            const ulonglong2* Wp = (const ulonglong2*)(g_w + (size_t)(base + j) * MITEMS);
            ulonglong2 w0 = Wp[0], w1 = Wp[1], w2 = Wp[2], w3 = Wp[3];   // broadcasts
            ulonglong2 w4 = Wp[4], w5 = Wp[5], w6 = Wp[6], w7 = Wp[7];
            u64 wm[MITEMS] = {w0.x, w0.y, w1.x, w1.y, w2.x, w2.y, w3.x, w3.y,
                              w4.x, w4.y, w5.x, w5.y, w6.x, w6.y, w7.x, w7.y};
            u64 o0 = 0ull, o1 = 0ull;
            #pragma unroll
            for (int m = 0; m < MITEMS; m++) {       // static indexing only
                FMA2(o0, V[m].x, wm[m]);
                FMA2(o1, V[m].y, wm[m]);
            }
            ulonglong2 v; v.x = o0; v.y = o1;
            ((ulonglong2*)(out_ret + (size_t)(base + j) * D))[p * 32 + lane] = v;
        }
    }
}

extern "C" void kernel_launch(void* const* d_in, const int* in_sizes, int n_in,
                              void* d_out, int out_size)
{
    const float* q   = (const float*)d_in[0];
    const float* mem = (const float*)d_in[1];
    int nrows = in_sizes[0] / D;              // 131072
    if (nrows > NROWS_MAX) nrows = NROWS_MAX;
    float* out_ret = (float*)d_out;
    float* out_max = out_ret + (size_t)nrows * D;

    cudaFuncSetAttribute(epm_dot_kernel,
                         cudaFuncAttributeMaxDynamicSharedMemorySize, SMEM1_BYTES);

    epm_dot_kernel<<<GRID, TPB, SMEM1_BYTES>>>(q, mem, out_max, nrows);
    epm_blend_kernel<<<GRID, TPB>>>(mem, out_ret, nrows);
}

// round 16
// speedup vs baseline: 1.4984x; 1.4984x over previous
#include <cuda_runtime.h>
#include <stdint.h>

#define D        256
#define MITEMS   16
#define TPB      256
#define NWARP    8
#define GRID     296           // 2 blocks/SM x 148 SMs: exactly one wave
#define RPW      56            // rows per warp: 296*8*56 = 132608 >= 131072
#define TILE     64            // staging capacity (tr <= 56 used)
#define CHUNK    8             // dims per pipeline chunk (32 B per row)
#define NCH      32
#define NBUF     3
#define QSTR     12            // staging row stride: 48B, LDS.128 conflict-free
#define BUFW     (TILE * QSTR) // 768 floats per buffer
#define RINGW    (NBUF * BUFW) // 2304 floats per warp ring
#define SM_MT    (NWARP * RINGW)            // 18432: mem_t offset
#define SM_RM    (SM_MT + MITEMS * D)       // 22528: mem_rm offset
#define SMEM_FLOATS (SM_RM + MITEMS * D)    // 26624 floats = 106496 B -> 2 blocks/SM
#define SMEM_BYTES  (SMEM_FLOATS * 4)
#define WSTR     20            // dense-W row stride inside the warp's dead ring
#define NEG_BIG (-1e30f)

typedef unsigned long long u64;

__device__ __forceinline__ u64 pack2(float lo, float hi) {
    u64 r; asm("mov.b64 %0, {%1, %2};" : "=l"(r) : "f"(lo), "f"(hi)); return r;
}
__device__ __forceinline__ void unpack2(u64 v, float& lo, float& hi) {
    asm("mov.b64 {%0, %1}, %2;" : "=f"(lo), "=f"(hi) : "l"(v));
}
#define FMA2(d, a, b) asm("fma.rn.f32x2 %0, %1, %2, %0;" : "+l"(d) : "l"(a), "l"(b))
#define CP16(dst, src) \
    asm volatile("cp.async.cg.shared.global [%0], [%1], 16;" :: "r"(dst), "l"(src))
#define CPCOMMIT() asm volatile("cp.async.commit_group;")
#define CPWAIT(n)  asm volatile("cp.async.wait_group %0;" :: "n"(n))

__global__ void __launch_bounds__(TPB, 2) epm_kernel(
    const float* __restrict__ q,
    const float* __restrict__ mem,
    float* __restrict__ out_ret,
    float* __restrict__ out_max,
    int nrows)
{
    extern __shared__ __align__(16) float sh[];
    const int tid  = threadIdx.x;
    const int wid  = tid >> 5;
    const int lane = tid & 31;

    float* ring   = sh + wid * RINGW;   // staging; aliased as dense-W rows after dot
    float* mem_t  = sh + SM_MT;         // [dim][16 items] (item pairs contiguous)
    float* mem_rm = sh + SM_RM;         // [item][256] for blend V loads
    const uint32_t ring_s = (uint32_t)__cvta_generic_to_shared(ring);

    // ---- warp work assignment (single tile per warp) ----
    const int base = (blockIdx.x * NWARP + wid) * RPW;
    int tr = nrows - base;
    if (tr > RPW) tr = RPW;

    // cp.async lane mapping: chunk = rows x 32B; lane covers rows rsub+16j
    const int rsub = lane >> 1;    // 0..15
    const int sub  = lane & 1;     // 16B slot

    // ---- prologue: issue chunks 0..2 BEFORE the setup barrier ----
    if (tr > 0) {
        #pragma unroll
        for (int c0 = 0; c0 < 3; c0++) {
            #pragma unroll
            for (int j = 0; j < 4; j++) {
                int rl = rsub + 16 * j;
                if (rl < tr) {
                    const float* src = q + (size_t)(base + rl) * D + c0 * CHUNK + sub * 4;
                    uint32_t dst = ring_s + (uint32_t)(c0 * BUFW + rl * QSTR + sub * 4) * 4u;
                    CP16(dst, src);
                }
            }
            CPCOMMIT();
        }
    }

    // ---- block-cooperative setup: mem_rm (float4) + mem_t (item-pair transpose) ----
    {
        const float4* s4 = (const float4*)mem;
        float4* d4 = (float4*)mem_rm;
        #pragma unroll
        for (int i = 0; i < (MITEMS * D / 4) / TPB; i++)   // 4 iters
            d4[tid + TPB * i] = s4[tid + TPB * i];
        #pragma unroll
        for (int i = 0; i < (MITEMS * D) / TPB; i++) {     // 16 iters
            int idx = tid + TPB * i;
            mem_t[(idx & 255) * MITEMS + (idx >> 8)] = mem[idx];
        }
    }
    __syncthreads();    // the ONLY block barrier

    if (tr <= 0) return;

    // ---- dot mainloop: item-pair-packed acc (s[2p],s[2p+1] per u64), ~106 regs ----
    u64 accA[8], accB[8];
    u64 ssqA2 = 0ull, ssqB2 = 0ull;
    #pragma unroll
    for (int p = 0; p < 8; p++) { accA[p] = 0ull; accB[p] = 0ull; }

    #pragma unroll 1
    for (int ct = 0; ct < NCH; ct++) {
        if (ct + 2 < NCH)      { CPWAIT(2); }
        else if (ct + 1 < NCH) { CPWAIT(1); }
        else                   { CPWAIT(0); }
        __syncwarp();

        const float* qb = ring + (ct % NBUF) * BUFW;
        #pragma unroll
        for (int h = 0; h < 2; h++) {
            ulonglong2 qA = *(const ulonglong2*)(qb + lane * QSTR + 4 * h);
            ulonglong2 qB = *(const ulonglong2*)(qb + (lane + 32) * QSTR + 4 * h);
            FMA2(ssqA2, qA.x, qA.x); FMA2(ssqA2, qA.y, qA.y);
            FMA2(ssqB2, qB.x, qB.x); FMA2(ssqB2, qB.y, qB.y);
            float a0, a1, a2, a3, b0, b1, b2, b3;
            unpack2(qA.x, a0, a1); unpack2(qA.y, a2, a3);
            unpack2(qB.x, b0, b1); unpack2(qB.y, b2, b3);
            u64 qqA[4] = {pack2(a0,a0), pack2(a1,a1), pack2(a2,a2), pack2(a3,a3)};
            u64 qqB[4] = {pack2(b0,b0), pack2(b1,b1), pack2(b2,b2), pack2(b3,b3)};
            #pragma unroll
            for (int d = 0; d < 4; d++) {
                const ulonglong2* mt =
                    (const ulonglong2*)(mem_t + (ct * CHUNK + 4 * h + d) * MITEMS);
                ulonglong2 v0 = mt[0], v1 = mt[1], v2 = mt[2], v3 = mt[3]; // broadcast
                FMA2(accA[0], v0.x, qqA[d]); FMA2(accA[1], v0.y, qqA[d]);
                FMA2(accA[2], v1.x, qqA[d]); FMA2(accA[3], v1.y, qqA[d]);
                FMA2(accA[4], v2.x, qqA[d]); FMA2(accA[5], v2.y, qqA[d]);
                FMA2(accA[6], v3.x, qqA[d]); FMA2(accA[7], v3.y, qqA[d]);
                FMA2(accB[0], v0.x, qqB[d]); FMA2(accB[1], v0.y, qqB[d]);
                FMA2(accB[2], v1.x, qqB[d]); FMA2(accB[3], v1.y, qqB[d]);
                FMA2(accB[4], v2.x, qqB[d]); FMA2(accB[5], v2.y, qqB[d]);
                FMA2(accB[6], v3.x, qqB[d]); FMA2(accB[7], v3.y, qqB[d]);
            }
        }
        __syncwarp();
        if (ct + 3 < NCH) {   // refill the just-freed buffer (WAR-safe)
            #pragma unroll
            for (int j = 0; j < 4; j++) {
                int rl = rsub + 16 * j;
                if (rl < tr) {
                    const float* src = q + (size_t)(base + rl) * D + (ct + 3) * CHUNK + sub * 4;
                    uint32_t dst = ring_s +
                        (uint32_t)(((ct + 3) % NBUF) * BUFW + rl * QSTR + sub * 4) * 4u;
                    CP16(dst, src);
                }
            }
            CPCOMMIT();
        }
    }
    __syncwarp();   // warp's ring fully consumed -> reuse as dense-W storage

    // ---- epilogue: 2 rows per lane -> dense W row in own ring + out_max ----
    #pragma unroll
    for (int r = 0; r < 2; r++) {
        int rl = lane + 32 * r;
        float s[MITEMS];
        #pragma unroll
        for (int p = 0; p < 8; p++)
            unpack2(r == 0 ? accA[p] : accB[p], s[2 * p], s[2 * p + 1]);
        float sl, shi; unpack2(r == 0 ? ssqA2 : ssqB2, sl, shi);
        float inv = rsqrtf(fmaxf(sl + shi, 1e-24f)) * 10.0f;  // (1/|q|)/tau; mem unit-norm
        #pragma unroll
        for (int m = 0; m < MITEMS; m++) s[m] *= inv;

        float bw[4]; int bi[4];
        #pragma unroll
        for (int k = 0; k < 4; k++) {
            float best = NEG_BIG; int b = 0;
            #pragma unroll
            for (int m = 0; m < MITEMS; m++)
                if (s[m] > best) { best = s[m]; b = m; }      // first-index ties
            bw[k] = best; bi[k] = b;
            #pragma unroll
            for (int m = 0; m < MITEMS; m++)
                s[m] = (m == b) ? NEG_BIG : s[m];
        }
        float e1 = __expf(bw[1] - bw[0]);
        float e2 = __expf(bw[2] - bw[0]);
        float e3 = __expf(bw[3] - bw[0]);
        float rden = 1.0f / (1.0f + e1 + e2 + e3);

        if (rl < tr) {
            float* Wr = ring + rl * WSTR;          // aliases dead staging ring
            float4 z = make_float4(0.f, 0.f, 0.f, 0.f);
            ((float4*)Wr)[0] = z;
            ((float4*)Wr)[1] = z;
            ((float4*)Wr)[2] = z;
            ((float4*)Wr)[3] = z;
            Wr[bi[0]] = rden;                      // smem scatter (safe)
            Wr[bi[1]] = e1 * rden;
            Wr[bi[2]] = e2 * rden;
            Wr[bi[3]] = e3 * rden;
            out_max[base + rl] = bw[0];
        }
    }
    __syncwarp();

    // ---- dense blend: two half-passes, V[16] regs (fits 128-reg cap, no spill) ----
    #pragma unroll 1
    for (int p = 0; p < 2; p++) {
        ulonglong2 V[MITEMS];                      // 64 regs, static indexing only
        const ulonglong2* mg = (const ulonglong2*)mem_rm;
        #pragma unroll
        for (int m = 0; m < MITEMS; m++)
            V[m] = mg[m * (D / 4) + p * 32 + lane];   // LDS.128 conflict-free

        #pragma unroll 2
        for (int j = 0; j < RPW; j++) {
            if (j >= tr) break;
            const float4* Wp = (const float4*)(ring + j * WSTR);   // smem broadcasts
            float4 w0 = Wp[0], w1 = Wp[1], w2 = Wp[2], w3 = Wp[3];
            float wv[16] = {w0.x, w0.y, w0.z, w0.w, w1.x, w1.y, w1.z, w1.w,
                            w2.x, w2.y, w2.z, w2.w, w3.x, w3.y, w3.z, w3.w};
            u64 o0 = 0ull, o1 = 0ull;
            #pragma unroll
            for (int m = 0; m < MITEMS; m++) {     // static indexing only
                u64 wm = pack2(wv[m], wv[m]);
                FMA2(o0, V[m].x, wm);
                FMA2(o1, V[m].y, wm);
            }
            ulonglong2 v; v.x = o0; v.y = o1;
            ((ulonglong2*)(out_ret + (size_t)(base + j) * D))[p * 32 + lane] = v;
        }
    }
}

extern "C" void kernel_launch(void* const* d_in, const int* in_sizes, int n_in,
                              void* d_out, int out_size)
{
    const float* q   = (const float*)d_in[0];
    const float* mem = (const float*)d_in[1];
    int nrows = in_sizes[0] / D;              // 131072
    float* out_ret = (float*)d_out;
    float* out_max = out_ret + (size_t)nrows * D;

    cudaFuncSetAttribute(epm_kernel,
                         cudaFuncAttributeMaxDynamicSharedMemorySize, SMEM_BYTES);

    epm_kernel<<<GRID, TPB, SMEM_BYTES>>>(q, mem, out_ret, out_max, nrows);
}

// round 17
// speedup vs baseline: 1.4991x; 1.0004x over previous
#include <cuda_runtime.h>
#include <stdint.h>

#define D        256
#define MITEMS   16
#define TPB      256
#define NWARP    8
#define GRID     296           // 2 blocks/SM x 148 SMs: exactly one wave
#define RPW      56            // rows per warp: 296*8*56 = 132608 >= 131072
#define TILE     64            // staging capacity (tr <= 56 used)
#define CHUNK    8             // dims per pipeline chunk (32 B per row)
#define NCH      32
#define NBUF     3
#define QSTR     12            // staging row stride: 48B, LDS.128 conflict-free
#define BUFW     (TILE * QSTR) // 768 floats per buffer
#define RINGW    (NBUF * BUFW) // 2304 floats per warp ring
#define SM_MT    (NWARP * RINGW)            // 18432: mem_t offset
#define SM_RM    (SM_MT + MITEMS * D)       // 22528: mem_rm offset
#define SMEM_FLOATS (SM_RM + MITEMS * D)    // 26624 floats = 106496 B -> 2 blocks/SM
#define SMEM_BYTES  (SMEM_FLOATS * 4)
#define WSTR     20            // dense-W row stride inside the warp's dead ring
#define NEG_BIG (-1e30f)

typedef unsigned long long u64;

__device__ __forceinline__ u64 pack2(float lo, float hi) {
    u64 r; asm("mov.b64 %0, {%1, %2};" : "=l"(r) : "f"(lo), "f"(hi)); return r;
}
__device__ __forceinline__ void unpack2(u64 v, float& lo, float& hi) {
    asm("mov.b64 {%0, %1}, %2;" : "=f"(lo), "=f"(hi) : "l"(v));
}
#define FMA2(d, a, b) asm("fma.rn.f32x2 %0, %1, %2, %0;" : "+l"(d) : "l"(a), "l"(b))
#define CP16(dst, src) \
    asm volatile("cp.async.cg.shared.global [%0], [%1], 16;" :: "r"(dst), "l"(src))
#define CPCOMMIT() asm volatile("cp.async.commit_group;")
#define CPWAIT(n)  asm volatile("cp.async.wait_group %0;" :: "n"(n))

__global__ void __launch_bounds__(TPB, 2) epm_kernel(
    const float* __restrict__ q,
    const float* __restrict__ mem,
    float* __restrict__ out_ret,
    float* __restrict__ out_max,
    int nrows)
{
    extern __shared__ __align__(16) float sh[];
    const int tid  = threadIdx.x;
    const int wid  = tid >> 5;
    const int lane = tid & 31;

    float* ring   = sh + wid * RINGW;   // staging; aliased as dense-W rows after dot
    float* mem_t  = sh + SM_MT;         // [dim][16 items] (item pairs contiguous)
    float* mem_rm = sh + SM_RM;         // [item][256] for blend V loads
    const uint32_t ring_s = (uint32_t)__cvta_generic_to_shared(ring);

    // ---- warp work assignment (single tile per warp) ----
    const int base = (blockIdx.x * NWARP + wid) * RPW;
    int tr = nrows - base;
    if (tr > RPW) tr = RPW;

    // cp.async lane mapping: chunk = rows x 32B; lane covers rows rsub+16j
    const int rsub = lane >> 1;    // 0..15
    const int sub  = lane & 1;     // 16B slot

    // ---- prologue: issue chunks 0..2 BEFORE the setup barrier ----
    if (tr > 0) {
        #pragma unroll
        for (int c0 = 0; c0 < 3; c0++) {
            #pragma unroll
            for (int j = 0; j < 4; j++) {
                int rl = rsub + 16 * j;
                if (rl < tr) {
                    const float* src = q + (size_t)(base + rl) * D + c0 * CHUNK + sub * 4;
                    uint32_t dst = ring_s + (uint32_t)(c0 * BUFW + rl * QSTR + sub * 4) * 4u;
                    CP16(dst, src);
                }
            }
            CPCOMMIT();
        }
    }

    // ---- block-cooperative setup: mem_rm (float4) + mem_t (item-pair transpose) ----
    {
        const float4* s4 = (const float4*)mem;
        float4* d4 = (float4*)mem_rm;
        #pragma unroll
        for (int i = 0; i < (MITEMS * D / 4) / TPB; i++)   // 4 iters
            d4[tid + TPB * i] = s4[tid + TPB * i];
        #pragma unroll
        for (int i = 0; i < (MITEMS * D) / TPB; i++) {     // 16 iters
            int idx = tid + TPB * i;
            mem_t[(idx & 255) * MITEMS + (idx >> 8)] = mem[idx];
        }
    }
    __syncthreads();    // the ONLY block barrier

    if (tr <= 0) return;

    // ---- dot mainloop: item-pair-packed acc (s[2p],s[2p+1] per u64), ~106 regs ----
    u64 accA[8], accB[8];
    u64 ssqA2 = 0ull, ssqB2 = 0ull;
    #pragma unroll
    for (int p = 0; p < 8; p++) { accA[p] = 0ull; accB[p] = 0ull; }

    #pragma unroll 1
    for (int ct = 0; ct < NCH; ct++) {
        if (ct + 2 < NCH)      { CPWAIT(2); }
        else if (ct + 1 < NCH) { CPWAIT(1); }
        else                   { CPWAIT(0); }
        __syncwarp();

        const float* qb = ring + (ct % NBUF) * BUFW;
        #pragma unroll
        for (int h = 0; h < 2; h++) {
            ulonglong2 qA = *(const ulonglong2*)(qb + lane * QSTR + 4 * h);
            ulonglong2 qB = *(const ulonglong2*)(qb + (lane + 32) * QSTR + 4 * h);
            FMA2(ssqA2, qA.x, qA.x); FMA2(ssqA2, qA.y, qA.y);
            FMA2(ssqB2, qB.x, qB.x); FMA2(ssqB2, qB.y, qB.y);
            float a0, a1, a2, a3, b0, b1, b2, b3;
            unpack2(qA.x, a0, a1); unpack2(qA.y, a2, a3);
            unpack2(qB.x, b0, b1); unpack2(qB.y, b2, b3);
            u64 qqA[4] = {pack2(a0,a0), pack2(a1,a1), pack2(a2,a2), pack2(a3,a3)};
            u64 qqB[4] = {pack2(b0,b0), pack2(b1,b1), pack2(b2,b2), pack2(b3,b3)};
            #pragma unroll
            for (int d = 0; d < 4; d++) {
                const ulonglong2* mt =
                    (const ulonglong2*)(mem_t + (ct * CHUNK + 4 * h + d) * MITEMS);
                ulonglong2 v0 = mt[0], v1 = mt[1], v2 = mt[2], v3 = mt[3]; // broadcast
                FMA2(accA[0], v0.x, qqA[d]); FMA2(accA[1], v0.y, qqA[d]);
                FMA2(accA[2], v1.x, qqA[d]); FMA2(accA[3], v1.y, qqA[d]);
                FMA2(accA[4], v2.x, qqA[d]); FMA2(accA[5], v2.y, qqA[d]);
                FMA2(accA[6], v3.x, qqA[d]); FMA2(accA[7], v3.y, qqA[d]);
                FMA2(accB[0], v0.x, qqB[d]); FMA2(accB[1], v0.y, qqB[d]);
                FMA2(accB[2], v1.x, qqB[d]); FMA2(accB[3], v1.y, qqB[d]);
                FMA2(accB[4], v2.x, qqB[d]); FMA2(accB[5], v2.y, qqB[d]);
                FMA2(accB[6], v3.x, qqB[d]); FMA2(accB[7], v3.y, qqB[d]);
            }
        }
        __syncwarp();
        if (ct + 3 < NCH) {   // refill the just-freed buffer (WAR-safe)
            #pragma unroll
            for (int j = 0; j < 4; j++) {
                int rl = rsub + 16 * j;
                if (rl < tr) {
                    const float* src = q + (size_t)(base + rl) * D + (ct + 3) * CHUNK + sub * 4;
                    uint32_t dst = ring_s +
                        (uint32_t)(((ct + 3) % NBUF) * BUFW + rl * QSTR + sub * 4) * 4u;
                    CP16(dst, src);
                }
            }
            CPCOMMIT();
        }
    }
    __syncwarp();   // warp's ring fully consumed -> reuse as dense-W storage

    // ---- epilogue: 2 rows per lane -> dense W row in own ring + out_max ----
    #pragma unroll
    for (int r = 0; r < 2; r++) {
        int rl = lane + 32 * r;
        float s[MITEMS];
        #pragma unroll
        for (int p = 0; p < 8; p++)
            unpack2(r == 0 ? accA[p] : accB[p], s[2 * p], s[2 * p + 1]);
        float sl, shi; unpack2(r == 0 ? ssqA2 : ssqB2, sl, shi);
        float inv = rsqrtf(fmaxf(sl + shi, 1e-24f)) * 10.0f;  // (1/|q|)/tau; mem unit-norm
        #pragma unroll
        for (int m = 0; m < MITEMS; m++) s[m] *= inv;

        float bw[4]; int bi[4];
        #pragma unroll
        for (int k = 0; k < 4; k++) {
            float best = NEG_BIG; int b = 0;
            #pragma unroll
            for (int m = 0; m < MITEMS; m++)
                if (s[m] > best) { best = s[m]; b = m; }      // first-index ties
            bw[k] = best; bi[k] = b;
            #pragma unroll
            for (int m = 0; m < MITEMS; m++)
                s[m] = (m == b) ? NEG_BIG : s[m];
        }
        float e1 = __expf(bw[1] - bw[0]);
        float e2 = __expf(bw[2] - bw[0]);
        float e3 = __expf(bw[3] - bw[0]);
        float rden = 1.0f / (1.0f + e1 + e2 + e3);

        if (rl < tr) {
            float* Wr = ring + rl * WSTR;          // aliases dead staging ring
            float4 z = make_float4(0.f, 0.f, 0.f, 0.f);
            ((float4*)Wr)[0] = z;
            ((float4*)Wr)[1] = z;
            ((float4*)Wr)[2] = z;
            ((float4*)Wr)[3] = z;
            Wr[bi[0]] = rden;                      // smem scatter (safe)
            Wr[bi[1]] = e1 * rden;
            Wr[bi[2]] = e2 * rden;
            Wr[bi[3]] = e3 * rden;
            out_max[base + rl] = bw[0];
        }
    }
    __syncwarp();

    // ---- dense blend: two half-passes, V[16] regs (fits 128-reg cap, no spill) ----
    #pragma unroll 1
    for (int p = 0; p < 2; p++) {
        ulonglong2 V[MITEMS];                      // 64 regs, static indexing only
        const ulonglong2* mg = (const ulonglong2*)mem_rm;
        #pragma unroll
        for (int m = 0; m < MITEMS; m++)
            V[m] = mg[m * (D / 4) + p * 32 + lane];   // LDS.128 conflict-free

        #pragma unroll 2
        for (int j = 0; j < RPW; j++) {
            if (j >= tr) break;
            const float4* Wp = (const float4*)(ring + j * WSTR);   // smem broadcasts
            float4 w0 = Wp[0], w1 = Wp[1], w2 = Wp[2], w3 = Wp[3];
            float wv[16] = {w0.x, w0.y, w0.z, w0.w, w1.x, w1.y, w1.z, w1.w,
                            w2.x, w2.y, w2.z, w2.w, w3.x, w3.y, w3.z, w3.w};
            u64 o0 = 0ull, o1 = 0ull;
            #pragma unroll
            for (int m = 0; m < MITEMS; m++) {     // static indexing only
                u64 wm = pack2(wv[m], wv[m]);
                FMA2(o0, V[m].x, wm);
                FMA2(o1, V[m].y, wm);
            }
            ulonglong2 v; v.x = o0; v.y = o1;
            ((ulonglong2*)(out_ret + (size_t)(base + j) * D))[p * 32 + lane] = v;
        }
    }
}

extern "C" void kernel_launch(void* const* d_in, const int* in_sizes, int n_in,
                              void* d_out, int out_size)
{
    const float* q   = (const float*)d_in[0];
    const float* mem = (const float*)d_in[1];
    int nrows = in_sizes[0] / D;              // 131072
    float* out_ret = (float*)d_out;
    float* out_max = out_ret + (size_t)nrows * D;

    cudaFuncSetAttribute(epm_kernel,
                         cudaFuncAttributeMaxDynamicSharedMemorySize, SMEM_BYTES);

    epm_kernel<<<GRID, TPB, SMEM_BYTES>>>(q, mem, out_ret, out_max, nrows);
}